// round 7
// baseline (speedup 1.0000x reference)
#include <cuda_runtime.h>

#define FINF __int_as_float(0x7f800000)

constexpr int BB = 32, HH = 512, WW = 512;
constexpr int TX = 128;          // output tile width
constexpr int TY = 32;           // output tile height
constexpr int R  = 7;            // k=15 radius
constexpr int DY = TY + 2 * R;   // 46 halo rows
constexpr int P1 = 148;          // dark smem pitch (floats): stride%32=20 -> conflict-free LDS.128 across rows
constexpr int P2 = 132;          // hmin smem pitch: stride%32=4  -> conflict-free STS.128 across rows
constexpr int NT = 256;
constexpr int SMEM_BYTES = (DY * P1 + DY * P2) * 4;  // 51520 B

__global__ __launch_bounds__(NT) void dark_erode_fused(const float* __restrict__ I,
                                                       float* __restrict__ O) {
    extern __shared__ float sm[];
    float* ds = sm;               // [DY][P1] channel-min (dark) halo tile
    float* hs = sm + DY * P1;     // [DY][P2] horizontally eroded tile

    const int tid = threadIdx.x;
    const int bx = blockIdx.x, by = blockIdx.y, b = blockIdx.z;
    const int gx0 = bx * TX - R;
    const int gy0 = by * TY - R;
    const float* base = I + (size_t)b * 3 * HH * WW;

    // ---- Phase 1: channel-min over 3 channels into ds (+inf out-of-bounds) ----
    // idx consecutive across warp -> consecutive gx -> fully coalesced loads.
    for (int idx = tid; idx < DY * P1; idx += NT) {
        const int r = idx / P1;
        const int c = idx - r * P1;
        const int gy = gy0 + r;
        const int gx = gx0 + c;
        float v = FINF;
        if ((unsigned)gx < (unsigned)WW && (unsigned)gy < (unsigned)HH) {
            const size_t o = (size_t)gy * WW + gx;
            const float a = __ldg(base + o);
            const float d = __ldg(base + o + HH * WW);
            const float e = __ldg(base + o + 2 * HH * WW);
            v = fminf(fminf(a, d), e);
        }
        ds[idx] = v;
    }
    __syncthreads();

    // ---- Phase 2: horizontal 15-tap min via window doubling ----
    // task = (x-chunk of 8 outputs) x (halo row). Consecutive tid -> consecutive row
    // -> LDS.128 at float-stride 148 -> conflict-free.
    for (int t = tid; t < (TX / 8) * DY; t += NT) {
        const int chunk = t / DY;
        const int r = t - chunk * DY;
        const int lx0 = chunk * 8;

        const float4* wp = reinterpret_cast<const float4*>(ds + r * P1 + lx0);
        float w[24];
#pragma unroll
        for (int i = 0; i < 6; i++) {
            float4 v = wp[i];
            w[4 * i + 0] = v.x; w[4 * i + 1] = v.y;
            w[4 * i + 2] = v.z; w[4 * i + 3] = v.w;
        }
        // out[j] = min over w[j .. j+14], j = 0..7
        float m2[22];
#pragma unroll
        for (int i = 0; i < 22; i++) m2[i] = fminf(w[i], w[i + 1]);
        float m4[19];
#pragma unroll
        for (int i = 0; i < 19; i++) m4[i] = fminf(m2[i], m2[i + 2]);
        float m8[15];
#pragma unroll
        for (int i = 0; i < 15; i++) m8[i] = fminf(m4[i], m4[i + 4]);

        float4 o0 = make_float4(fminf(m8[0], m8[7]),  fminf(m8[1], m8[8]),
                                fminf(m8[2], m8[9]),  fminf(m8[3], m8[10]));
        float4 o1 = make_float4(fminf(m8[4], m8[11]), fminf(m8[5], m8[12]),
                                fminf(m8[6], m8[13]), fminf(m8[7], m8[14]));
        float4* hp = reinterpret_cast<float4*>(hs + r * P2 + lx0);
        hp[0] = o0;
        hp[1] = o1;
    }
    __syncthreads();

    // ---- Phase 3: vertical 15-tap min via window doubling, coalesced output ----
    // task = (column lx) x (y-group of 8). Consecutive tid -> consecutive lx
    // -> stride-1 smem (conflict-free) and coalesced STG.
    for (int t = tid; t < TX * (TY / 8); t += NT) {
        const int yg = t >> 7;        // t / 128
        const int lx = t & 127;
        const int r0 = yg * 8;        // hs row base (= local output row base)

        const float* cp = hs + r0 * P2 + lx;
        float w[22];
#pragma unroll
        for (int i = 0; i < 22; i++) w[i] = cp[i * P2];

        float m2[21];
#pragma unroll
        for (int i = 0; i < 21; i++) m2[i] = fminf(w[i], w[i + 1]);
        float m4[19];
#pragma unroll
        for (int i = 0; i < 19; i++) m4[i] = fminf(m2[i], m2[i + 2]);
        float m8[15];
#pragma unroll
        for (int i = 0; i < 15; i++) m8[i] = fminf(m4[i], m4[i + 4]);

        const int gy = by * TY + r0;
        float* op = O + ((size_t)b * HH + gy) * WW + bx * TX + lx;
#pragma unroll
        for (int j = 0; j < 8; j++) {
            op[(size_t)j * WW] = fminf(m8[j], m8[j + 7]);
        }
    }
}

extern "C" void kernel_launch(void* const* d_in, const int* in_sizes, int n_in,
                              void* d_out, int out_size) {
    // Find I by element count (robust to metadata ordering; k=15 baked in).
    const float* I = (const float*)d_in[0];
    for (int i = 0; i < n_in; i++) {
        if (in_sizes[i] == BB * 3 * HH * WW) I = (const float*)d_in[i];
    }
    float* out = (float*)d_out;

    static bool attr_done = false;
    (void)cudaFuncSetAttribute(dark_erode_fused,
                               cudaFuncAttributeMaxDynamicSharedMemorySize,
                               SMEM_BYTES);
    (void)attr_done;

    dim3 grid(WW / TX, HH / TY, BB);   // (4, 16, 32) = 2048 blocks
    dark_erode_fused<<<grid, NT, SMEM_BYTES>>>(I, out);
}

// round 8
// speedup vs baseline: 1.5234x; 1.5234x over previous
#include <cuda_runtime.h>

#define FINF __int_as_float(0x7f800000)

constexpr int BB = 32, HH = 512, WW = 512;
constexpr int TX = 128;           // tile width (outputs)
constexpr int TY = 64;            // tile height (outputs)
constexpr int R  = 7;             // k=15 radius
constexpr int DY = TY + 2 * R;    // 78 halo rows
constexpr int NT = 256;           // 8 warps

__global__ __launch_bounds__(NT) void dark_erode(const float* __restrict__ I,
                                                 float* __restrict__ O) {
    __shared__ float hs[DY * TX];  // horizontally-eroded halo tile, pitch 128

    const int tid  = threadIdx.x;
    const int lane = tid & 31;
    const int warp = tid >> 5;
    const int bx = blockIdx.x, by = blockIdx.y, b = blockIdx.z;
    const int W0 = bx * TX;
    const int x0 = W0 + 4 * lane;          // own 4-float block
    const float* base = I + (size_t)b * 3 * HH * WW;

    // ---- Phase A: coalesced load + channel-min + horizontal 15-min via shuffles ----
    // Warp w handles halo rows w, w+8, ... Each lane produces 4 outputs/row.
    for (int r = warp; r < DY; r += NT / 32) {
        const int gy = by * TY - R + r;
        const bool rowv = (unsigned)gy < (unsigned)HH;

        float4 d = make_float4(FINF, FINF, FINF, FINF);  // block i   (own)
        float4 g = d;                                    // block i-2 (x0-8)
        float4 e = d;                                    // block i+2 for lanes 30/31 (x0+8)
        if (rowv) {
            const float* r0 = base + (size_t)gy * WW;
            const float* r1 = r0 + HH * WW;
            const float* r2 = r1 + HH * WW;
            {
                float4 a = *(const float4*)(r0 + x0);
                float4 c = *(const float4*)(r1 + x0);
                float4 f = *(const float4*)(r2 + x0);
                d.x = fminf(fminf(a.x, c.x), f.x);
                d.y = fminf(fminf(a.y, c.y), f.y);
                d.z = fminf(fminf(a.z, c.z), f.z);
                d.w = fminf(fminf(a.w, c.w), f.w);
            }
            if (x0 - 8 >= 0) {
                float4 a = *(const float4*)(r0 + x0 - 8);
                float4 c = *(const float4*)(r1 + x0 - 8);
                float4 f = *(const float4*)(r2 + x0 - 8);
                g.x = fminf(fminf(a.x, c.x), f.x);
                g.y = fminf(fminf(a.y, c.y), f.y);
                g.z = fminf(fminf(a.z, c.z), f.z);
                g.w = fminf(fminf(a.w, c.w), f.w);
            }
            if (lane >= 30 && x0 + 8 < WW) {
                float4 a = *(const float4*)(r0 + x0 + 8);
                float4 c = *(const float4*)(r1 + x0 + 8);
                float4 f = *(const float4*)(r2 + x0 + 8);
                e.x = fminf(fminf(a.x, c.x), f.x);
                e.y = fminf(fminf(a.y, c.y), f.y);
                e.z = fminf(fminf(a.z, c.z), f.z);
                e.w = fminf(fminf(a.w, c.w), f.w);
            }
        }

        // per-block stats
        const float Pd0 = d.x;
        const float Pd1 = fminf(d.x, d.y);
        const float Pd2 = fminf(Pd1, d.z);
        const float F   = fminf(Pd2, d.w);
        const float Sg3 = g.w;
        const float Sg2 = fminf(g.z, g.w);
        const float Sg1 = fminf(g.y, Sg2);
        const float Fg  = fminf(g.x, Sg1);
        const float Pe0 = e.x;
        const float Pe1 = fminf(e.x, e.y);
        const float Pe2 = fminf(Pe1, e.z);
        const float Fe  = fminf(Pe2, e.w);

        // cross-lane gathers (all lanes participate; edges patched by select)
        const unsigned m = 0xffffffffu;
        const float upF  = __shfl_up_sync(m, F, 1);
        const float dnF  = __shfl_down_sync(m, F, 1);
        const float dnFg = __shfl_down_sync(m, Fg, 1);
        const float upFe = __shfl_up_sync(m, Fe, 1);
        const float dnP0 = __shfl_down_sync(m, Pd0, 2);
        const float dnP1 = __shfl_down_sync(m, Pd1, 2);
        const float dnP2 = __shfl_down_sync(m, Pd2, 2);

        const float FL1 = (lane == 0)  ? dnFg : upF;   // full min of block i-1
        const float FR  = (lane == 31) ? upFe : dnF;   // full min of block i+1
        const float Q0  = (lane >= 30) ? Pe0 : dnP0;   // prefix of block i+2
        const float Q1  = (lane >= 30) ? Pe1 : dnP1;
        const float Q2  = (lane >= 30) ? Pe2 : dnP2;

        const float core = fminf(FL1, fminf(F, FR));
        float4 o;
        o.x = fminf(core, Sg1);               // window [x0-7 , x0+7 ]
        o.y = fminf(fminf(core, Sg2), Q0);    // window [x0-6 , x0+8 ]
        o.z = fminf(fminf(core, Sg3), Q1);    // window [x0-5 , x0+9 ]
        o.w = fminf(core, Q2);                // window [x0-4 , x0+10]

        *(float4*)(hs + r * TX + 4 * lane) = o;
    }
    __syncthreads();

    // ---- Phase B: vertical 15-tap min from smem, coalesced output ----
    // task = (column lx) x (y-group of 8). Lane stride 1 float -> conflict-free LDS.
    for (int t = tid; t < TX * (TY / 8); t += NT) {
        const int lx = t & (TX - 1);
        const int yg = t >> 7;                 // TX = 128
        const float* cp = hs + (yg * 8) * TX + lx;

        float w[22];
#pragma unroll
        for (int i = 0; i < 22; i++) w[i] = cp[i * TX];
        // in-place window doubling: m2, m4, m8
#pragma unroll
        for (int i = 0; i < 21; i++) w[i] = fminf(w[i], w[i + 1]);
#pragma unroll
        for (int i = 0; i < 19; i++) w[i] = fminf(w[i], w[i + 2]);
#pragma unroll
        for (int i = 0; i < 15; i++) w[i] = fminf(w[i], w[i + 4]);

        float* op = O + ((size_t)b * HH + by * TY + yg * 8) * WW + W0 + lx;
#pragma unroll
        for (int j = 0; j < 8; j++) {
            op[(size_t)j * WW] = fminf(w[j], w[j + 7]);
        }
    }
}

extern "C" void kernel_launch(void* const* d_in, const int* in_sizes, int n_in,
                              void* d_out, int out_size) {
    // Find I by element count (robust to metadata ordering; k=15 baked in).
    const float* I = (const float*)d_in[0];
    for (int i = 0; i < n_in; i++) {
        if (in_sizes[i] == BB * 3 * HH * WW) I = (const float*)d_in[i];
    }
    float* out = (float*)d_out;

    dim3 grid(WW / TX, HH / TY, BB);   // (4, 8, 32) = 1024 blocks
    dark_erode<<<grid, NT>>>(I, out);
}